// round 1
// baseline (speedup 1.0000x reference)
#include <cuda_runtime.h>
#include <cstdint>

#define BB 8
#define TT 400
#define FFD 256
#define NN (TT*FFD)        // 102400 points per batch
#define DD 64
#define KK 16
#define ITERS 5
#define PPC 1024           // points per estep CTA
#define CHUNKS (NN/PPC)    // 100
#define ST 256             // subtile points (== threads)
#define NSUB (PPC/ST)      // 4
#define SLOTS (2*KK*DD + KK)   // 2064: sx[K][D], sx2[K][D], cs[K]
#define NTH 256

#define XSTRIDE 68         // padded row stride (floats) for sX to dodge bank conflicts

// ---------------- device scratch (no allocations allowed) ----------------
__device__ float g_AB[BB*KK*DD*2];                       // interleaved: [b][k][dp] = {A[2dp],A[2dp+1],B[2dp],B[2dp+1]}
__device__ float g_C[BB*KK];                             // per-(b,k) constant term
__device__ float g_part[(size_t)BB*CHUNKS*SLOTS];        // per-chunk partial stats (deterministic reduction)

// ---------------- packed f32x2 helpers (Blackwell) ----------------
__device__ __forceinline__ unsigned long long f2fma(unsigned long long a, unsigned long long b, unsigned long long c) {
    unsigned long long d;
    asm("fma.rn.f32x2 %0, %1, %2, %3;" : "=l"(d) : "l"(a), "l"(b), "l"(c));
    return d;
}
__device__ __forceinline__ unsigned long long f2mul(unsigned long long a, unsigned long long b) {
    unsigned long long d;
    asm("mul.rn.f32x2 %0, %1, %2;" : "=l"(d) : "l"(a), "l"(b));
    return d;
}
__device__ __forceinline__ unsigned long long f2add(unsigned long long a, unsigned long long b) {
    unsigned long long d;
    asm("add.rn.f32x2 %0, %1, %2;" : "=l"(d) : "l"(a), "l"(b));
    return d;
}
__device__ __forceinline__ unsigned long long fpack2(float lo, float hi) {
    unsigned long long r;
    asm("mov.b64 %0, {%1, %2};" : "=l"(r) : "f"(lo), "f"(hi));
    return r;
}
__device__ __forceinline__ float2 funpack2(unsigned long long v) {
    float2 f;
    asm("mov.b64 {%0, %1}, %2;" : "=f"(f.x), "=f"(f.y) : "l"(v));
    return f;
}

// Fused logits for one point (thread-private), x row in padded SMEM, params in SMEM.
// logit[k] = C[k] + sum_d ( x*A[k][d] + x^2 * B[k][d] )  via  x*(x*B + A)
__device__ __forceinline__ void compute_logits(const float* __restrict__ xrow,
                                               const float* __restrict__ sAB,
                                               const float* __restrict__ sC,
                                               float* __restrict__ logit) {
    unsigned long long acc[KK];
#pragma unroll
    for (int k = 0; k < KK; ++k) acc[k] = 0ull;

#pragma unroll 1
    for (int db = 0; db < 4; ++db) {            // 4 blocks of 16 floats (8 pairs)
        const ulonglong2* xr = (const ulonglong2*)(xrow + db * 16);
        ulonglong2 xa = xr[0], xb = xr[1], xc = xr[2], xd = xr[3];
        unsigned long long xp[8] = {xa.x, xa.y, xb.x, xb.y, xc.x, xc.y, xd.x, xd.y};
        const ulonglong2* abp = ((const ulonglong2*)sAB) + db * 8;
#pragma unroll
        for (int k = 0; k < KK; ++k) {
            const ulonglong2* a = abp + k * 32;
#pragma unroll
            for (int j = 0; j < 8; ++j) {
                ulonglong2 t = a[j];                    // {Apair, Bpair}
                unsigned long long u = f2fma(xp[j], t.y, t.x);   // x*B + A
                acc[k] = f2fma(xp[j], u, acc[k]);                // x*(x*B+A) + acc
            }
        }
    }
#pragma unroll
    for (int k = 0; k < KK; ++k) {
        float2 f = funpack2(acc[k]);
        logit[k] = sC[k] + f.x + f.y;
    }
}

// ---------------- E-step: fused logits + softmax + stat accumulation ----------------
// SMEM layout (floats): sAB[2048] | sC[16] | sX[256*68] | sPost[16*256]
__global__ void __launch_bounds__(NTH, 2)
k_estep(const float* __restrict__ data) {
    extern __shared__ float sm[];
    float* sAB   = sm;
    float* sC    = sm + 2048;
    float* sX    = sm + 2064;
    float* sPost = sm + 2064 + ST * XSTRIDE;

    const int tid   = threadIdx.x;
    const int chunk = blockIdx.x;
    const int b     = blockIdx.y;

    // load params
    {
        const float4* g4 = ((const float4*)g_AB) + (size_t)b * (KK * DD / 2);
        float4* s4 = (float4*)sAB;
        for (int i = tid; i < 512; i += NTH) s4[i] = g4[i];
        if (tid < KK) sC[tid] = g_C[b * KK + tid];
    }

    // per-thread register accumulators for the GEMM-style phase B tile (k, 4 d's)
    unsigned long long s0 = 0ull, s1 = 0ull, q0 = 0ull, q1 = 0ull;
    float csum = 0.f;
    const int kk = tid >> 4;        // 0..15
    const int dg = tid & 15;        // 0..15 -> d in [dg*4, dg*4+4)

    const float* xg = data + ((size_t)b * NN + (size_t)chunk * PPC) * DD;

    for (int s = 0; s < NSUB; ++s) {
        __syncthreads();   // also covers the param load on s==0
        // stage 256 points x 64 floats (coalesced), padded rows
        {
            const float4* src = (const float4*)(xg + (size_t)s * ST * DD);
#pragma unroll 4
            for (int i = tid; i < ST * DD / 4; i += NTH) {
                int p = i >> 4, j = i & 15;
                ((float4*)sX)[p * 17 + j] = src[i];
            }
        }
        __syncthreads();

        // phase A: one point per thread
        float logit[KK];
        compute_logits(sX + tid * XSTRIDE, sAB, sC, logit);

        // softmax over K=16
        float mx = logit[0];
#pragma unroll
        for (int k = 1; k < KK; ++k) mx = fmaxf(mx, logit[k]);
        float ssum = 0.f;
#pragma unroll
        for (int k = 0; k < KK; ++k) { float e = __expf(logit[k] - mx); logit[k] = e; ssum += e; }
        float rinv = 1.f / ssum;
#pragma unroll
        for (int k = 0; k < KK; ++k) sPost[k * ST + tid] = logit[k] * rinv;
        __syncthreads();

        // phase B: register-tiled accumulation, thread owns (kk, d = dg*4..dg*4+3)
        const float* prow = sPost + kk * ST;
        const float* xcol = sX + dg * 4;
#pragma unroll 2
        for (int n = 0; n < ST; n += 4) {
            float4 pv = *(const float4*)(prow + n);
#pragma unroll
            for (int u4 = 0; u4 < 4; ++u4) {
                float p = (u4 == 0) ? pv.x : (u4 == 1) ? pv.y : (u4 == 2) ? pv.z : pv.w;
                ulonglong2 xv = *(const ulonglong2*)(xcol + (size_t)(n + u4) * XSTRIDE);
                unsigned long long pp = fpack2(p, p);
                unsigned long long m0 = f2mul(pp, xv.x);
                unsigned long long m1 = f2mul(pp, xv.y);
                s0 = f2add(s0, m0);
                s1 = f2add(s1, m1);
                q0 = f2fma(m0, xv.x, q0);
                q1 = f2fma(m1, xv.y, q1);
                csum += p;
            }
        }
    }

    // deterministic per-chunk partial write
    float* dst = g_part + ((size_t)(b * CHUNKS + chunk)) * SLOTS;
    float2 a0 = funpack2(s0), a1 = funpack2(s1), b0 = funpack2(q0), b1 = funpack2(q1);
    *(float4*)(dst + kk * DD + dg * 4)           = make_float4(a0.x, a0.y, a1.x, a1.y);
    *(float4*)(dst + KK * DD + kk * DD + dg * 4) = make_float4(b0.x, b0.y, b1.x, b1.y);
    if (dg == 0) dst[2 * KK * DD + kk] = csum;
}

// ---------------- M-step: reduce partials + rebuild params ----------------
__global__ void k_mstep(const float* __restrict__ init_means, int init) {
    __shared__ float acc[SLOTS];
    const int b = blockIdx.x, tid = threadIdx.x;

    if (!init) {
        const float* base = g_part + (size_t)b * CHUNKS * SLOTS;
        for (int s = tid; s < SLOTS; s += NTH) {
            float v = 0.f;
#pragma unroll 4
            for (int c = 0; c < CHUNKS; ++c) v += base[(size_t)c * SLOTS + s];
            acc[s] = v;
        }
        __syncthreads();
    }

    const int k = tid >> 4, dg = tid & 15;
    float cs = 0.f, pi;
    if (init) {
        pi = 1.0f / KK;
    } else {
        cs = acc[2 * KK * DD + k];
        float csumall = 0.f;
#pragma unroll
        for (int j = 0; j < KK; ++j) csumall += acc[2 * KK * DD + j];
        pi = cs / csumall;
    }

    float plog = 0.f, pmmi = 0.f;
    float A[4], Bc[4];
#pragma unroll
    for (int t = 0; t < 4; ++t) {
        int d = dg * 4 + t;
        float m, var;
        if (init) {
            m = init_means[((size_t)b * KK + k) * DD + d];
            var = 1.0f;                                     // COV_INIT
        } else {
            float sx  = acc[k * DD + d];
            float sx2 = acc[KK * DD + k * DD + d];
            m   = sx / (cs + 1e-7f);
            var = sx2 - 2.0f * m * sx + m * m * cs + 1e-6f; // stored var
        }
        float inv = 1.0f / (var + 1e-6f);
        plog += logf(6.283185307179586f * var);
        pmmi += m * m * inv;
        A[t]  = m * inv;
        Bc[t] = -0.5f * inv;
    }

    // interleaved {A0,A1,B0,B1} per d-pair
    float4* ab4 = ((float4*)g_AB) + ((size_t)b * KK + k) * 32;
    ab4[dg * 2]     = make_float4(A[0], A[1], Bc[0], Bc[1]);
    ab4[dg * 2 + 1] = make_float4(A[2], A[3], Bc[2], Bc[3]);

    // reduce plog/pmmi over the 16 lanes of each k-group (lanes 16-aligned in warp)
#pragma unroll
    for (int o = 8; o >= 1; o >>= 1) {
        plog += __shfl_xor_sync(0xffffffffu, plog, o);
        pmmi += __shfl_xor_sync(0xffffffffu, pmmi, o);
    }
    if (dg == 0) g_C[b * KK + k] = logf(pi) - 0.5f * plog - 0.5f * pmmi;
}

// ---------------- Final: logits -> sigmoid -> [B,T,F,K] ----------------
// SMEM: sAB[2048] | sC[16] | sX[256*68]
__global__ void __launch_bounds__(NTH, 2)
k_final(const float* __restrict__ data, const float* __restrict__ scale,
        const float* __restrict__ bias, float* __restrict__ out) {
    extern __shared__ float sm[];
    float* sAB = sm;
    float* sC  = sm + 2048;
    float* sX  = sm + 2064;

    const int tid  = threadIdx.x;
    const int tile = blockIdx.x;   // 0..399
    const int b    = blockIdx.y;

    {
        const float4* g4 = ((const float4*)g_AB) + (size_t)b * (KK * DD / 2);
        float4* s4 = (float4*)sAB;
        for (int i = tid; i < 512; i += NTH) s4[i] = g4[i];
        if (tid < KK) sC[tid] = g_C[b * KK + tid];
    }
    {
        const float4* src = (const float4*)(data + ((size_t)b * NN + (size_t)tile * ST) * DD);
#pragma unroll 4
        for (int i = tid; i < ST * DD / 4; i += NTH) {
            int p = i >> 4, j = i & 15;
            ((float4*)sX)[p * 17 + j] = src[i];
        }
    }
    __syncthreads();

    float logit[KK];
    compute_logits(sX + tid * XSTRIDE, sAB, sC, logit);

    const float sc = scale[0], bs = bias[0];
    float outv[KK];
#pragma unroll
    for (int k = 0; k < KK; ++k) {
        float z = logit[k] * sc + bs;
        float e = __expf(-fabsf(z));
        float q = e / (1.f + e);                 // = sigmoid(-|z|)
        outv[k] = (z >= 0.f) ? (1.f - q) : q;
    }

    float* o = out + ((size_t)b * NN + (size_t)tile * ST + tid) * KK;
    const float4* ov4 = (const float4*)outv;
#pragma unroll
    for (int j = 0; j < 4; ++j) ((float4*)o)[j] = ov4[j];
}

// ---------------- host launcher (graph-capturable) ----------------
extern "C" void kernel_launch(void* const* d_in, const int* in_sizes, int n_in,
                              void* d_out, int out_size) {
    const float* data  = (const float*)d_in[0];
    const float* means = (const float*)d_in[1];
    const float* scale = (const float*)d_in[2];
    const float* bias  = (const float*)d_in[3];
    float* out = (float*)d_out;

    const int smem_e = (2064 + ST * XSTRIDE + KK * ST) * 4;   // 94272
    const int smem_f = (2064 + ST * XSTRIDE) * 4;             // 77888
    cudaFuncSetAttribute(k_estep, cudaFuncAttributeMaxDynamicSharedMemorySize, smem_e);
    cudaFuncSetAttribute(k_final, cudaFuncAttributeMaxDynamicSharedMemorySize, smem_f);

    dim3 ge(CHUNKS, BB);
    dim3 gf(NN / ST, BB);

    k_mstep<<<BB, NTH>>>(means, 1);
    for (int i = 0; i < ITERS; ++i) {
        k_estep<<<ge, NTH, smem_e>>>(data);
        k_mstep<<<BB, NTH>>>(means, 0);
    }
    k_final<<<gf, NTH, smem_f>>>(data, scale, bias, out);
}

// round 2
// speedup vs baseline: 1.1360x; 1.1360x over previous
#include <cuda_runtime.h>
#include <cstdint>

#define BB 8
#define TT 400
#define FFD 256
#define NN (TT*FFD)        // 102400 points per batch
#define DD 64
#define KK 16
#define ITERS 5
#define PPC 1024           // points per estep CTA
#define CHUNKS (NN/PPC)    // 100
#define ST 256             // subtile points (== threads)
#define NSUB (PPC/ST)      // 4
#define SLOTS (2*KK*DD + KK)   // 2064: sx[K][D], sx2[K][D], cs[K]
#define NTH 256

#define XSTRIDE 68         // padded row stride (floats) for sX
#define PSTR 20            // padded row stride for transposed posteriors

// ---------------- device scratch (no allocations allowed) ----------------
__device__ float g_AB[BB*KK*DD*2];                       // [b][k][dp] = {A0,A1,B0,B1}
__device__ float g_C[BB*KK];                             // per-(b,k) constant term
__device__ float g_part[(size_t)BB*CHUNKS*SLOTS];        // per-chunk partials

// ---------------- packed f32x2 helpers (Blackwell) ----------------
__device__ __forceinline__ unsigned long long f2fma(unsigned long long a, unsigned long long b, unsigned long long c) {
    unsigned long long d;
    asm("fma.rn.f32x2 %0, %1, %2, %3;" : "=l"(d) : "l"(a), "l"(b), "l"(c));
    return d;
}
__device__ __forceinline__ unsigned long long f2mul(unsigned long long a, unsigned long long b) {
    unsigned long long d;
    asm("mul.rn.f32x2 %0, %1, %2;" : "=l"(d) : "l"(a), "l"(b));
    return d;
}
__device__ __forceinline__ unsigned long long f2add(unsigned long long a, unsigned long long b) {
    unsigned long long d;
    asm("add.rn.f32x2 %0, %1, %2;" : "=l"(d) : "l"(a), "l"(b));
    return d;
}
__device__ __forceinline__ unsigned long long fpack2(float lo, float hi) {
    unsigned long long r;
    asm("mov.b64 %0, {%1, %2};" : "=l"(r) : "f"(lo), "f"(hi));
    return r;
}
__device__ __forceinline__ float2 funpack2(unsigned long long v) {
    float2 f;
    asm("mov.b64 {%0, %1}, %2;" : "=f"(f.x), "=f"(f.y) : "l"(v));
    return f;
}

// Register-tiled logits: thread computes 4 points x 4 clusters.
// acc[pt][kk] accumulates sum_d x*(x*B + A) as f32x2.
__device__ __forceinline__ void logits_tile(const float* __restrict__ xrow0,   // sX + (warp*32+pslot)*XSTRIDE
                                            const float* __restrict__ abbase, // sAB + kslot*4*128
                                            unsigned long long acc[4][4]) {
#pragma unroll
    for (int pt = 0; pt < 4; ++pt)
#pragma unroll
        for (int kk = 0; kk < 4; ++kk) acc[pt][kk] = 0ull;

#pragma unroll 4
    for (int it = 0; it < 16; ++it) {          // 2 d-pairs per iteration
        ulonglong2 xq[4];
#pragma unroll
        for (int pt = 0; pt < 4; ++pt)
            xq[pt] = *(const ulonglong2*)(xrow0 + pt * 8 * XSTRIDE + it * 4);
#pragma unroll
        for (int kk = 0; kk < 4; ++kk) {
            ulonglong2 ab0 = *(const ulonglong2*)(abbase + kk * 128 + it * 8);      // {A01,B01}
            ulonglong2 ab1 = *(const ulonglong2*)(abbase + kk * 128 + it * 8 + 4);  // {A23,B23}
#pragma unroll
            for (int pt = 0; pt < 4; ++pt) {
                unsigned long long u0 = f2fma(xq[pt].x, ab0.y, ab0.x);
                acc[pt][kk] = f2fma(xq[pt].x, u0, acc[pt][kk]);
                unsigned long long u1 = f2fma(xq[pt].y, ab1.y, ab1.x);
                acc[pt][kk] = f2fma(xq[pt].y, u1, acc[pt][kk]);
            }
        }
    }
}

// ---------------- E-step ----------------
// SMEM (floats): sAB[2048] | sC[16] | sX[256*68] | sPostT[256*20]
__global__ void __launch_bounds__(NTH, 2)
k_estep(const float* __restrict__ data) {
    extern __shared__ float sm[];
    float* sAB    = sm;
    float* sC     = sm + 2048;
    float* sX     = sm + 2064;
    float* sPostT = sm + 2064 + ST * XSTRIDE;

    const int tid   = threadIdx.x;
    const int lane  = tid & 31;
    const int warp  = tid >> 5;
    const int pslot = lane & 7;
    const int kslot = lane >> 3;
    const int chunk = blockIdx.x;
    const int b     = blockIdx.y;

    // phase-B mapping: thread owns clusters kg*4..+3, dims dg*4..+3, points n = 4i+rep
    const int kg  = tid >> 6;
    const int rep = (tid >> 4) & 3;
    const int dg  = tid & 15;

    // load params
    {
        const float4* g4 = ((const float4*)g_AB) + (size_t)b * (KK * DD / 2);
        float4* s4 = (float4*)sAB;
        for (int i = tid; i < 512; i += NTH) s4[i] = g4[i];
        if (tid < KK) sC[tid] = g_C[b * KK + tid];
    }

    // persistent phase-B accumulators: (4 clusters) x (4 dims as 2 f32x2) for s and q
    unsigned long long sacc[4][2], qacc[4][2];
    float csum[4];
#pragma unroll
    for (int kk = 0; kk < 4; ++kk) {
        sacc[kk][0] = sacc[kk][1] = 0ull;
        qacc[kk][0] = qacc[kk][1] = 0ull;
        csum[kk] = 0.f;
    }

    const float* xg = data + ((size_t)b * NN + (size_t)chunk * PPC) * DD;

    for (int s = 0; s < NSUB; ++s) {
        __syncthreads();   // protects sX from phase B of previous subtile (and param load on s==0)
        {
            const float4* src = (const float4*)(xg + (size_t)s * ST * DD);
#pragma unroll 4
            for (int i = tid; i < ST * DD / 4; i += NTH) {
                int p = i >> 4, j = i & 15;
                ((float4*)sX)[p * 17 + j] = src[i];
            }
        }
        __syncthreads();

        // ---- phase A: tiled logits + softmax ----
        unsigned long long acc[4][4];
        logits_tile(sX + (warp * 32 + pslot) * XSTRIDE, sAB + kslot * 4 * 128, acc);

#pragma unroll
        for (int pt = 0; pt < 4; ++pt) {
            float l[4];
#pragma unroll
            for (int kk = 0; kk < 4; ++kk) {
                float2 f = funpack2(acc[pt][kk]);
                l[kk] = sC[kslot * 4 + kk] + f.x + f.y;
            }
            float mx = fmaxf(fmaxf(l[0], l[1]), fmaxf(l[2], l[3]));
            mx = fmaxf(mx, __shfl_xor_sync(0xffffffffu, mx, 8));
            mx = fmaxf(mx, __shfl_xor_sync(0xffffffffu, mx, 16));
            float e0 = __expf(l[0] - mx), e1 = __expf(l[1] - mx);
            float e2 = __expf(l[2] - mx), e3 = __expf(l[3] - mx);
            float ssum = (e0 + e1) + (e2 + e3);
            ssum += __shfl_xor_sync(0xffffffffu, ssum, 8);
            ssum += __shfl_xor_sync(0xffffffffu, ssum, 16);
            float inv = 1.f / ssum;
            int p = warp * 32 + pslot + pt * 8;
            *(float4*)(sPostT + p * PSTR + kslot * 4) =
                make_float4(e0 * inv, e1 * inv, e2 * inv, e3 * inv);
        }
        __syncthreads();

        // ---- phase B: accumulate sx, sx2, cs (thread tile: 4k x 4d, 64 points) ----
#pragma unroll 2
        for (int i = 0; i < 64; ++i) {
            int n = i * 4 + rep;
            float4 pv = *(const float4*)(sPostT + n * PSTR + kg * 4);
            ulonglong2 xv = *(const ulonglong2*)(sX + n * XSTRIDE + dg * 4);
#pragma unroll
            for (int kk = 0; kk < 4; ++kk) {
                float p = (&pv.x)[kk];
                unsigned long long pp = fpack2(p, p);
                unsigned long long m0 = f2mul(pp, xv.x);
                unsigned long long m1 = f2mul(pp, xv.y);
                sacc[kk][0] = f2add(sacc[kk][0], m0);
                sacc[kk][1] = f2add(sacc[kk][1], m1);
                qacc[kk][0] = f2fma(m0, xv.x, qacc[kk][0]);
                qacc[kk][1] = f2fma(m1, xv.y, qacc[kk][1]);
                csum[kk] += p;
            }
        }
    }

    // ---- reduce the 4 point-replicas via smem, write one deterministic partial ----
    __syncthreads();
    float* sRed = sX;   // reuse: 4 * SLOTS = 8256 floats <= 17408
#pragma unroll
    for (int kk = 0; kk < 4; ++kk) {
        int k = kg * 4 + kk;
        float2 a0 = funpack2(sacc[kk][0]), a1 = funpack2(sacc[kk][1]);
        float2 b0 = funpack2(qacc[kk][0]), b1 = funpack2(qacc[kk][1]);
        *(float4*)(sRed + rep * SLOTS + k * DD + dg * 4) = make_float4(a0.x, a0.y, a1.x, a1.y);
        *(float4*)(sRed + rep * SLOTS + KK * DD + k * DD + dg * 4) = make_float4(b0.x, b0.y, b1.x, b1.y);
        if (dg == 0) sRed[rep * SLOTS + 2 * KK * DD + k] = csum[kk];
    }
    __syncthreads();
    float* dst = g_part + ((size_t)(b * CHUNKS + chunk)) * SLOTS;
    for (int i = tid; i < SLOTS; i += NTH)
        dst[i] = (sRed[i] + sRed[SLOTS + i]) + (sRed[2 * SLOTS + i] + sRed[3 * SLOTS + i]);
}

// ---------------- M-step: reduce partials + rebuild params ----------------
__global__ void k_mstep(const float* __restrict__ init_means, int init) {
    __shared__ float acc[SLOTS];
    const int b = blockIdx.x, tid = threadIdx.x;

    if (!init) {
        const float* base = g_part + (size_t)b * CHUNKS * SLOTS;
        for (int s = tid; s < SLOTS; s += NTH) {
            float v = 0.f;
#pragma unroll 4
            for (int c = 0; c < CHUNKS; ++c) v += base[(size_t)c * SLOTS + s];
            acc[s] = v;
        }
        __syncthreads();
    }

    const int k = tid >> 4, dg = tid & 15;
    float cs = 0.f, pi;
    if (init) {
        pi = 1.0f / KK;
    } else {
        cs = acc[2 * KK * DD + k];
        float csumall = 0.f;
#pragma unroll
        for (int j = 0; j < KK; ++j) csumall += acc[2 * KK * DD + j];
        pi = cs / csumall;
    }

    float plog = 0.f, pmmi = 0.f;
    float A[4], Bc[4];
#pragma unroll
    for (int t = 0; t < 4; ++t) {
        int d = dg * 4 + t;
        float m, var;
        if (init) {
            m = init_means[((size_t)b * KK + k) * DD + d];
            var = 1.0f;                                     // COV_INIT
        } else {
            float sx  = acc[k * DD + d];
            float sx2 = acc[KK * DD + k * DD + d];
            m   = sx / (cs + 1e-7f);
            var = sx2 - 2.0f * m * sx + m * m * cs + 1e-6f;
        }
        float inv = 1.0f / (var + 1e-6f);
        plog += logf(6.283185307179586f * var);
        pmmi += m * m * inv;
        A[t]  = m * inv;
        Bc[t] = -0.5f * inv;
    }

    float4* ab4 = ((float4*)g_AB) + ((size_t)b * KK + k) * 32;
    ab4[dg * 2]     = make_float4(A[0], A[1], Bc[0], Bc[1]);
    ab4[dg * 2 + 1] = make_float4(A[2], A[3], Bc[2], Bc[3]);

#pragma unroll
    for (int o = 8; o >= 1; o >>= 1) {
        plog += __shfl_xor_sync(0xffffffffu, plog, o);
        pmmi += __shfl_xor_sync(0xffffffffu, pmmi, o);
    }
    if (dg == 0) g_C[b * KK + k] = logf(pi) - 0.5f * plog - 0.5f * pmmi;
}

// ---------------- Final: logits -> sigmoid -> [B,T,F,K] ----------------
// SMEM: sAB[2048] | sC[16] | sX[256*68]
__global__ void __launch_bounds__(NTH, 2)
k_final(const float* __restrict__ data, const float* __restrict__ scale,
        const float* __restrict__ bias, float* __restrict__ out) {
    extern __shared__ float sm[];
    float* sAB = sm;
    float* sC  = sm + 2048;
    float* sX  = sm + 2064;

    const int tid   = threadIdx.x;
    const int lane  = tid & 31;
    const int warp  = tid >> 5;
    const int pslot = lane & 7;
    const int kslot = lane >> 3;
    const int tile  = blockIdx.x;   // 0..399
    const int b     = blockIdx.y;

    {
        const float4* g4 = ((const float4*)g_AB) + (size_t)b * (KK * DD / 2);
        float4* s4 = (float4*)sAB;
        for (int i = tid; i < 512; i += NTH) s4[i] = g4[i];
        if (tid < KK) sC[tid] = g_C[b * KK + tid];
    }
    {
        const float4* src = (const float4*)(data + ((size_t)b * NN + (size_t)tile * ST) * DD);
#pragma unroll 4
        for (int i = tid; i < ST * DD / 4; i += NTH) {
            int p = i >> 4, j = i & 15;
            ((float4*)sX)[p * 17 + j] = src[i];
        }
    }
    __syncthreads();

    unsigned long long acc[4][4];
    logits_tile(sX + (warp * 32 + pslot) * XSTRIDE, sAB + kslot * 4 * 128, acc);

    const float sc = scale[0], bs = bias[0];
#pragma unroll
    for (int pt = 0; pt < 4; ++pt) {
        float o[4];
#pragma unroll
        for (int kk = 0; kk < 4; ++kk) {
            float2 f = funpack2(acc[pt][kk]);
            float z = (sC[kslot * 4 + kk] + f.x + f.y) * sc + bs;
            float e = __expf(-fabsf(z));
            float q = e / (1.f + e);
            o[kk] = (z >= 0.f) ? (1.f - q) : q;
        }
        int p = warp * 32 + pslot + pt * 8;
        float* og = out + ((size_t)b * NN + (size_t)tile * ST + p) * KK + kslot * 4;
        *(float4*)og = make_float4(o[0], o[1], o[2], o[3]);
    }
}

// ---------------- host launcher (graph-capturable) ----------------
extern "C" void kernel_launch(void* const* d_in, const int* in_sizes, int n_in,
                              void* d_out, int out_size) {
    const float* data  = (const float*)d_in[0];
    const float* means = (const float*)d_in[1];
    const float* scale = (const float*)d_in[2];
    const float* bias  = (const float*)d_in[3];
    float* out = (float*)d_out;

    const int smem_e = (2064 + ST * XSTRIDE + ST * PSTR) * 4;   // 98368
    const int smem_f = (2064 + ST * XSTRIDE) * 4;               // 77888
    cudaFuncSetAttribute(k_estep, cudaFuncAttributeMaxDynamicSharedMemorySize, smem_e);
    cudaFuncSetAttribute(k_final, cudaFuncAttributeMaxDynamicSharedMemorySize, smem_f);

    dim3 ge(CHUNKS, BB);
    dim3 gf(NN / ST, BB);

    k_mstep<<<BB, NTH>>>(means, 1);
    for (int i = 0; i < ITERS; ++i) {
        k_estep<<<ge, NTH, smem_e>>>(data);
        k_mstep<<<BB, NTH>>>(means, 0);
    }
    k_final<<<gf, NTH, smem_f>>>(data, scale, bias, out);
}

// round 3
// speedup vs baseline: 1.5048x; 1.3247x over previous
#include <cuda_runtime.h>
#include <cstdint>

#define BB 8
#define TT 400
#define FFD 256
#define NN (TT*FFD)        // 102400 points per batch
#define DD 64
#define KK 16
#define ITERS 5
#define PPC 1024           // points per estep CTA
#define CHUNKS (NN/PPC)    // 100
#define ST 128             // subtile points (double-buffered)
#define NSUB (PPC/ST)      // 8
#define SLOTS (2*KK*DD + KK)   // 2064
#define NTH 256

#define XSTRIDE 68         // padded row stride (floats) for sX
#define PSTR 20            // padded row stride for transposed posteriors

// ---------------- device scratch ----------------
__device__ float g_AB[BB*KK*DD*2];                 // [b][k][dp] = {A0,A1,B0,B1}
__device__ float g_C[BB*KK];
__device__ float g_part[(size_t)BB*CHUNKS*SLOTS];  // per-chunk partials
__device__ float g_sum[BB*SLOTS];                  // reduced stats

// ---------------- packed f32x2 helpers ----------------
__device__ __forceinline__ unsigned long long f2fma(unsigned long long a, unsigned long long b, unsigned long long c) {
    unsigned long long d;
    asm("fma.rn.f32x2 %0, %1, %2, %3;" : "=l"(d) : "l"(a), "l"(b), "l"(c));
    return d;
}
__device__ __forceinline__ unsigned long long f2mul(unsigned long long a, unsigned long long b) {
    unsigned long long d;
    asm("mul.rn.f32x2 %0, %1, %2;" : "=l"(d) : "l"(a), "l"(b));
    return d;
}
__device__ __forceinline__ unsigned long long fpack2(float lo, float hi) {
    unsigned long long r;
    asm("mov.b64 %0, {%1, %2};" : "=l"(r) : "f"(lo), "f"(hi));
    return r;
}
__device__ __forceinline__ float2 funpack2(unsigned long long v) {
    float2 f;
    asm("mov.b64 {%0, %1}, %2;" : "=f"(f.x), "=f"(f.y) : "l"(v));
    return f;
}

// ---------------- cp.async helpers ----------------
__device__ __forceinline__ void cp16(uint32_t saddr, const void* g) {
    asm volatile("cp.async.ca.shared.global [%0], [%1], 16;" :: "r"(saddr), "l"(g));
}
__device__ __forceinline__ void cp_commit() { asm volatile("cp.async.commit_group;"); }
template<int N> __device__ __forceinline__ void cp_wait() {
    asm volatile("cp.async.wait_group %0;" :: "n"(N));
}
__device__ __forceinline__ uint32_t s2u(const void* p) {
    return (uint32_t)__cvta_generic_to_shared(p);
}

// stage ST=128 points (2048 float4) into padded smem buffer via cp.async
__device__ __forceinline__ void stage(uint32_t sbuf, const float* __restrict__ src, int tid) {
#pragma unroll
    for (int r = 0; r < 8; ++r) {
        int i = tid + r * NTH;               // 0..2047
        int p = i >> 4, j = i & 15;
        cp16(sbuf + (uint32_t)(p * 17 + j) * 16, src + (size_t)i * 4);
    }
}

// Register-tiled logits: thread computes 2 points x 4 clusters.
__device__ __forceinline__ void logits_tile2(const float* __restrict__ xrow0,   // point p0; p1 = p0 + 8 rows
                                             const float* __restrict__ abk,    // sAB + kslot*512
                                             unsigned long long acc[2][4]) {
#pragma unroll
    for (int pt = 0; pt < 2; ++pt)
#pragma unroll
        for (int kk = 0; kk < 4; ++kk) acc[pt][kk] = 0ull;

#pragma unroll 4
    for (int it = 0; it < 16; ++it) {
        ulonglong2 x0 = *(const ulonglong2*)(xrow0 + it * 4);
        ulonglong2 x1 = *(const ulonglong2*)(xrow0 + 8 * XSTRIDE + it * 4);
#pragma unroll
        for (int kk = 0; kk < 4; ++kk) {
            ulonglong2 ab0 = *(const ulonglong2*)(abk + kk * 128 + it * 8);
            ulonglong2 ab1 = *(const ulonglong2*)(abk + kk * 128 + it * 8 + 4);
            unsigned long long u;
            u = f2fma(x0.x, ab0.y, ab0.x); acc[0][kk] = f2fma(x0.x, u, acc[0][kk]);
            u = f2fma(x0.y, ab1.y, ab1.x); acc[0][kk] = f2fma(x0.y, u, acc[0][kk]);
            u = f2fma(x1.x, ab0.y, ab0.x); acc[1][kk] = f2fma(x1.x, u, acc[1][kk]);
            u = f2fma(x1.y, ab1.y, ab1.x); acc[1][kk] = f2fma(x1.y, u, acc[1][kk]);
        }
    }
}

// ---------------- E-step ----------------
// SMEM (floats): sAB[2048] | sC[16] | sX0[128*68] | sX1[128*68] | sPostT[128*20]
__global__ void __launch_bounds__(NTH, 2)
k_estep(const float* __restrict__ data) {
    extern __shared__ float sm[];
    float* sAB    = sm;
    float* sC     = sm + 2048;
    float* sX0    = sm + 2064;
    float* sX1    = sX0 + ST * XSTRIDE;
    float* sPostT = sX1 + ST * XSTRIDE;

    const int tid   = threadIdx.x;
    const int lane  = tid & 31;
    const int warp  = tid >> 5;
    const int pslot = lane & 7;
    const int kslot = lane >> 3;
    const int chunk = blockIdx.x;
    const int b     = blockIdx.y;

    // phase-B mapping: clusters kg*4..+3, dims dg*4..+3, points n = 4i+rep
    const int kg  = tid >> 6;
    const int rep = (tid >> 4) & 3;
    const int dg  = tid & 15;

    const float* xg = data + ((size_t)b * NN + (size_t)chunk * PPC) * DD;
    const uint32_t uX0 = s2u(sX0), uX1 = s2u(sX1);

    // prologue: prefetch subtile 0, load params
    stage(uX0, xg, tid);
    cp_commit();
    {
        const float4* g4 = ((const float4*)g_AB) + (size_t)b * (KK * DD / 2);
        float4* s4 = (float4*)sAB;
        for (int i = tid; i < 512; i += NTH) s4[i] = g4[i];
        if (tid < KK) sC[tid] = g_C[b * KK + tid];
    }

    // persistent phase-B accumulators
    unsigned long long sacc[4][2], qacc[4][2];
    float csum[4];
#pragma unroll
    for (int kk = 0; kk < 4; ++kk) {
        sacc[kk][0] = sacc[kk][1] = 0ull;
        qacc[kk][0] = qacc[kk][1] = 0ull;
        csum[kk] = 0.f;
    }

    for (int s = 0; s < NSUB; ++s) {
        float* sX = (s & 1) ? sX1 : sX0;
        // prefetch next subtile into the other buffer (free: phase B of s-1 done before
        // the barrier that ended the previous loop body / prologue has no conflict)
        if (s + 1 < NSUB) {
            stage((s & 1) ? uX0 : uX1, xg + (size_t)(s + 1) * ST * DD, tid);
            cp_commit();
            cp_wait<1>();
        } else {
            cp_wait<0>();
        }
        __syncthreads();

        // ---- phase A: tiled logits + softmax ----
        unsigned long long acc[2][4];
        logits_tile2(sX + (warp * 16 + pslot) * XSTRIDE, sAB + kslot * 512, acc);

#pragma unroll
        for (int pt = 0; pt < 2; ++pt) {
            float l[4];
#pragma unroll
            for (int kk = 0; kk < 4; ++kk) {
                float2 f = funpack2(acc[pt][kk]);
                l[kk] = sC[kslot * 4 + kk] + f.x + f.y;
            }
            float mx = fmaxf(fmaxf(l[0], l[1]), fmaxf(l[2], l[3]));
            mx = fmaxf(mx, __shfl_xor_sync(0xffffffffu, mx, 8));
            mx = fmaxf(mx, __shfl_xor_sync(0xffffffffu, mx, 16));
            float e0 = __expf(l[0] - mx), e1 = __expf(l[1] - mx);
            float e2 = __expf(l[2] - mx), e3 = __expf(l[3] - mx);
            float ssum = (e0 + e1) + (e2 + e3);
            ssum += __shfl_xor_sync(0xffffffffu, ssum, 8);
            ssum += __shfl_xor_sync(0xffffffffu, ssum, 16);
            float inv = 1.f / ssum;
            int p = warp * 16 + pslot + pt * 8;
            *(float4*)(sPostT + p * PSTR + kslot * 4) =
                make_float4(e0 * inv, e1 * inv, e2 * inv, e3 * inv);
        }
        __syncthreads();

        // ---- phase B: accumulate sx, sx2, cs ----
#pragma unroll 2
        for (int i = 0; i < ST / 4; ++i) {
            int n = i * 4 + rep;
            float4 pv = *(const float4*)(sPostT + n * PSTR + kg * 4);
            ulonglong2 xv = *(const ulonglong2*)(sX + n * XSTRIDE + dg * 4);
            unsigned long long x2a = f2mul(xv.x, xv.x);
            unsigned long long x2b = f2mul(xv.y, xv.y);
#pragma unroll
            for (int kk = 0; kk < 4; ++kk) {
                float p = (&pv.x)[kk];
                unsigned long long pp = fpack2(p, p);
                sacc[kk][0] = f2fma(pp, xv.x, sacc[kk][0]);
                sacc[kk][1] = f2fma(pp, xv.y, sacc[kk][1]);
                qacc[kk][0] = f2fma(pp, x2a, qacc[kk][0]);
                qacc[kk][1] = f2fma(pp, x2b, qacc[kk][1]);
                csum[kk] += p;
            }
        }
        __syncthreads();   // protects sX (prefetch target next iter) and sPostT
    }

    // ---- reduce the 4 point-replicas via smem, write one deterministic partial ----
    float* sRed = sX0;   // 4*SLOTS = 8256 floats <= 8704 (one buffer)
#pragma unroll
    for (int kk = 0; kk < 4; ++kk) {
        int k = kg * 4 + kk;
        float2 a0 = funpack2(sacc[kk][0]), a1 = funpack2(sacc[kk][1]);
        float2 b0 = funpack2(qacc[kk][0]), b1 = funpack2(qacc[kk][1]);
        *(float4*)(sRed + rep * SLOTS + k * DD + dg * 4) = make_float4(a0.x, a0.y, a1.x, a1.y);
        *(float4*)(sRed + rep * SLOTS + KK * DD + k * DD + dg * 4) = make_float4(b0.x, b0.y, b1.x, b1.y);
        if (dg == 0) sRed[rep * SLOTS + 2 * KK * DD + k] = csum[kk];
    }
    __syncthreads();
    float* dst = g_part + ((size_t)(b * CHUNKS + chunk)) * SLOTS;
    for (int i = tid; i < SLOTS; i += NTH)
        dst[i] = (sRed[i] + sRed[SLOTS + i]) + (sRed[2 * SLOTS + i] + sRed[3 * SLOTS + i]);
}

// ---------------- parallel inter-chunk reduction ----------------
__global__ void k_reduce() {
    const int b = blockIdx.y;
    const int s = blockIdx.x * NTH + threadIdx.x;
    if (s >= SLOTS) return;
    const float* base = g_part + (size_t)b * CHUNKS * SLOTS + s;
    float v = 0.f;
#pragma unroll 4
    for (int c = 0; c < CHUNKS; ++c) v += base[(size_t)c * SLOTS];
    g_sum[b * SLOTS + s] = v;
}

// ---------------- parameter rebuild ----------------
__global__ void k_params(const float* __restrict__ init_means, int init) {
    __shared__ float acc[SLOTS];
    const int b = blockIdx.x, tid = threadIdx.x;

    if (!init) {
        for (int s = tid; s < SLOTS; s += NTH) acc[s] = g_sum[b * SLOTS + s];
        __syncthreads();
    }

    const int k = tid >> 4, dg = tid & 15;
    float cs = 0.f, pi;
    if (init) {
        pi = 1.0f / KK;
    } else {
        cs = acc[2 * KK * DD + k];
        float csumall = 0.f;
#pragma unroll
        for (int j = 0; j < KK; ++j) csumall += acc[2 * KK * DD + j];
        pi = cs / csumall;
    }

    float plog = 0.f, pmmi = 0.f;
    float A[4], Bc[4];
#pragma unroll
    for (int t = 0; t < 4; ++t) {
        int d = dg * 4 + t;
        float m, var;
        if (init) {
            m = init_means[((size_t)b * KK + k) * DD + d];
            var = 1.0f;                                     // COV_INIT
        } else {
            float sx  = acc[k * DD + d];
            float sx2 = acc[KK * DD + k * DD + d];
            m   = sx / (cs + 1e-7f);
            var = sx2 - 2.0f * m * sx + m * m * cs + 1e-6f;
        }
        float inv = 1.0f / (var + 1e-6f);
        plog += logf(6.283185307179586f * var);
        pmmi += m * m * inv;
        A[t]  = m * inv;
        Bc[t] = -0.5f * inv;
    }

    float4* ab4 = ((float4*)g_AB) + ((size_t)b * KK + k) * 32;
    ab4[dg * 2]     = make_float4(A[0], A[1], Bc[0], Bc[1]);
    ab4[dg * 2 + 1] = make_float4(A[2], A[3], Bc[2], Bc[3]);

#pragma unroll
    for (int o = 8; o >= 1; o >>= 1) {
        plog += __shfl_xor_sync(0xffffffffu, plog, o);
        pmmi += __shfl_xor_sync(0xffffffffu, pmmi, o);
    }
    if (dg == 0) g_C[b * KK + k] = logf(pi) - 0.5f * plog - 0.5f * pmmi;
}

// ---------------- Final: logits -> sigmoid -> [B,T,F,K] ----------------
// SMEM: sAB[2048] | sC[16] | sX0[128*68] | sX1[128*68]
__global__ void __launch_bounds__(NTH, 2)
k_final(const float* __restrict__ data, const float* __restrict__ scale,
        const float* __restrict__ bias, float* __restrict__ out) {
    extern __shared__ float sm[];
    float* sAB = sm;
    float* sC  = sm + 2048;
    float* sX0 = sm + 2064;
    float* sX1 = sX0 + ST * XSTRIDE;

    const int tid   = threadIdx.x;
    const int lane  = tid & 31;
    const int warp  = tid >> 5;
    const int pslot = lane & 7;
    const int kslot = lane >> 3;
    const int chunk = blockIdx.x;
    const int b     = blockIdx.y;

    const float* xg = data + ((size_t)b * NN + (size_t)chunk * PPC) * DD;
    const uint32_t uX0 = s2u(sX0), uX1 = s2u(sX1);

    stage(uX0, xg, tid);
    cp_commit();
    {
        const float4* g4 = ((const float4*)g_AB) + (size_t)b * (KK * DD / 2);
        float4* s4 = (float4*)sAB;
        for (int i = tid; i < 512; i += NTH) s4[i] = g4[i];
        if (tid < KK) sC[tid] = g_C[b * KK + tid];
    }
    const float sc = scale[0], bs = bias[0];

    for (int s = 0; s < NSUB; ++s) {
        float* sX = (s & 1) ? sX1 : sX0;
        if (s + 1 < NSUB) {
            stage((s & 1) ? uX0 : uX1, xg + (size_t)(s + 1) * ST * DD, tid);
            cp_commit();
            cp_wait<1>();
        } else {
            cp_wait<0>();
        }
        __syncthreads();

        unsigned long long acc[2][4];
        logits_tile2(sX + (warp * 16 + pslot) * XSTRIDE, sAB + kslot * 512, acc);

#pragma unroll
        for (int pt = 0; pt < 2; ++pt) {
            float o[4];
#pragma unroll
            for (int kk = 0; kk < 4; ++kk) {
                float2 f = funpack2(acc[pt][kk]);
                float z = (sC[kslot * 4 + kk] + f.x + f.y) * sc + bs;
                float e = __expf(-fabsf(z));
                float q = e / (1.f + e);
                o[kk] = (z >= 0.f) ? (1.f - q) : q;
            }
            int p = warp * 16 + pslot + pt * 8;
            float* og = out + ((size_t)b * NN + (size_t)chunk * PPC + (size_t)s * ST + p) * KK + kslot * 4;
            *(float4*)og = make_float4(o[0], o[1], o[2], o[3]);
        }
        __syncthreads();   // sX reused as prefetch target next iteration
    }
}

// ---------------- host launcher (graph-capturable) ----------------
extern "C" void kernel_launch(void* const* d_in, const int* in_sizes, int n_in,
                              void* d_out, int out_size) {
    const float* data  = (const float*)d_in[0];
    const float* means = (const float*)d_in[1];
    const float* scale = (const float*)d_in[2];
    const float* bias  = (const float*)d_in[3];
    float* out = (float*)d_out;

    const int smem_e = (2064 + 2 * ST * XSTRIDE + ST * PSTR) * 4;   // 88128
    const int smem_f = (2064 + 2 * ST * XSTRIDE) * 4;               // 77888
    cudaFuncSetAttribute(k_estep, cudaFuncAttributeMaxDynamicSharedMemorySize, smem_e);
    cudaFuncSetAttribute(k_final, cudaFuncAttributeMaxDynamicSharedMemorySize, smem_f);

    dim3 ge(CHUNKS, BB);
    dim3 gr((SLOTS + NTH - 1) / NTH, BB);
    dim3 gf(CHUNKS, BB);

    k_params<<<BB, NTH>>>(means, 1);
    for (int i = 0; i < ITERS; ++i) {
        k_estep<<<ge, NTH, smem_e>>>(data);
        k_reduce<<<gr, NTH>>>();
        k_params<<<BB, NTH>>>(means, 0);
    }
    k_final<<<gf, NTH, smem_f>>>(data, scale, bias, out);
}